// round 12
// baseline (speedup 1.0000x reference)
#include <cuda_runtime.h>

#define Nn 100000
#define Ee 1600000
#define Dd 128
#define Gg 64
#define EPSBN 1e-5f
#define PADA 132

typedef unsigned long long u64t;

__device__ float g_h[Nn * Dd];
__device__ float g_aggr[Nn * Dd];
__device__ float g_sums[Gg * Dd];
__device__ float g_cnt[Gg];

// ---- packed fp32 helpers (Blackwell f32x2) --------------------------------
__device__ __forceinline__ void ffma2(u64t& d, u64t a, u64t b) {
    asm("fma.rn.f32x2 %0, %1, %2, %0;" : "+l"(d) : "l"(a), "l"(b));
}
__device__ __forceinline__ u64t rep2(float x) {
    u64t r; asm("mov.b64 %0, {%1, %1};" : "=l"(r) : "f"(x)); return r;
}
__device__ __forceinline__ float2 unpk(u64t v) {
    float2 f; asm("mov.b64 {%0, %1}, %2;" : "=f"(f.x), "=f"(f.y) : "l"(v)); return f;
}

// ---- shared-tile MMA: 8 edges x 8 channels per thread ---------------------
template <int KMAX>
__device__ __forceinline__ void mma_chunk(const float* __restrict__ sA,
                                          const float* __restrict__ sB,
                                          u64t acc[8][4], int e0, int c0) {
#pragma unroll 8
    for (int k = 0; k < KMAX; k++) {
        float4 a01 = *(const float4*)(sA + k * PADA + e0);
        float4 a23 = *(const float4*)(sA + k * PADA + e0 + 4);
        const u64t* br = (const u64t*)(sB + k * Dd + c0);
        u64t b0 = br[0], b1 = br[1], b2 = br[2], b3 = br[3];
        u64t av;
        av = rep2(a01.x); ffma2(acc[0][0], av, b0); ffma2(acc[0][1], av, b1); ffma2(acc[0][2], av, b2); ffma2(acc[0][3], av, b3);
        av = rep2(a01.y); ffma2(acc[1][0], av, b0); ffma2(acc[1][1], av, b1); ffma2(acc[1][2], av, b2); ffma2(acc[1][3], av, b3);
        av = rep2(a01.z); ffma2(acc[2][0], av, b0); ffma2(acc[2][1], av, b1); ffma2(acc[2][2], av, b2); ffma2(acc[2][3], av, b3);
        av = rep2(a01.w); ffma2(acc[3][0], av, b0); ffma2(acc[3][1], av, b1); ffma2(acc[3][2], av, b2); ffma2(acc[3][3], av, b3);
        av = rep2(a23.x); ffma2(acc[4][0], av, b0); ffma2(acc[4][1], av, b1); ffma2(acc[4][2], av, b2); ffma2(acc[4][3], av, b3);
        av = rep2(a23.y); ffma2(acc[5][0], av, b0); ffma2(acc[5][1], av, b1); ffma2(acc[5][2], av, b2); ffma2(acc[5][3], av, b3);
        av = rep2(a23.z); ffma2(acc[6][0], av, b0); ffma2(acc[6][1], av, b1); ffma2(acc[6][2], av, b2); ffma2(acc[6][3], av, b3);
        av = rep2(a23.w); ffma2(acc[7][0], av, b0); ffma2(acc[7][1], av, b1); ffma2(acc[7][2], av, b2); ffma2(acc[7][3], av, b3);
    }
}

// ---------------------------------------------------------------------------
__global__ void lin_in_kernel(const float* __restrict__ x, const float* __restrict__ pos,
                              const float* __restrict__ w, const float* __restrict__ b,
                              float* __restrict__ h) {
    int n = blockIdx.x;
    int c = threadIdx.x;
    __shared__ float f[14];
    if (c < 11) f[c] = x[n * 11 + c];
    else if (c < 14) f[c] = pos[n * 3 + (c - 11)];
    __syncthreads();
    float acc = b[c];
#pragma unroll
    for (int k = 0; k < 14; k++) acc = fmaf(f[k], w[k * Dd + c], acc);
    h[n * Dd + c] = acc;
}

// ---------------------------------------------------------------------------
// Edge kernel: 128-edge tile. GEMM1 (K=260) -> relu/BN -> GEMM2 (K=128)
// -> relu -> atomic scatter-add. sA layout is k-major [k][edge] (PADA=132).
// ---------------------------------------------------------------------------
__global__ __launch_bounds__(256, 2) void edge_kernel(
    const float* __restrict__ h, const int* __restrict__ src, const int* __restrict__ dst,
    const float* __restrict__ ea,
    const float* __restrict__ w1, const float* __restrict__ b1,
    const float* __restrict__ bng, const float* __restrict__ bnb,
    const float* __restrict__ bnm, const float* __restrict__ bnv,
    const float* __restrict__ w2, const float* __restrict__ b2,
    float* __restrict__ aggr) {
    extern __shared__ float smem[];
    float* sM = smem;                 // [128][PADA]
    float* sA = smem;                 // overlay: [32][PADA]
    float* sB = smem + 128 * PADA;    // [32][128]
    __shared__ int sDst[128], sSrc[128];

    const int tid = threadIdx.x;
    const int cx = tid & 15, ey = tid >> 4;
    const int c0 = cx * 8, e0 = ey * 8;
    const int ebase = blockIdx.x * 128;

    if (tid < 128) {
        sDst[tid] = dst[ebase + tid];
        sSrc[tid] = src[ebase + tid];
    }

    const int kq = tid & 7;    // k-quad for staging
    const int er = tid >> 3;   // 0..31

    u64t acc[8][4];
#pragma unroll
    for (int i = 0; i < 8; i++)
#pragma unroll
        for (int j = 0; j < 4; j++) acc[i][j] = 0ull;

    // ----- GEMM1: chunks 0..7 = h[dst]|h[src] ------------------------------
    for (int kc = 0; kc < 8; kc++) {
        __syncthreads();
        {
            const int koff = (kc & 3) * 32 + kq * 4;
            const int* nodes = (kc < 4) ? sDst : sSrc;
#pragma unroll
            for (int p = 0; p < 4; p++) {
                int e = er + p * 32;
                int node = nodes[e];
                float4 v = *(const float4*)&h[(size_t)node * Dd + koff];
                sA[(kq * 4 + 0) * PADA + e] = v.x;
                sA[(kq * 4 + 1) * PADA + e] = v.y;
                sA[(kq * 4 + 2) * PADA + e] = v.z;
                sA[(kq * 4 + 3) * PADA + e] = v.w;
            }
        }
        {
            const float* wsrc = w1 + (size_t)(kc * 32) * Dd;
#pragma unroll
            for (int i = 0; i < 4; i++) {
                int li = tid + i * 256;
                *(float4*)&sB[li * 4] = *(const float4*)&wsrc[li * 4];
            }
        }
        __syncthreads();
        mma_chunk<32>(sA, sB, acc, e0, c0);
    }

    // ----- GEMM1: ragged chunk (edge_attr, 4 k) ----------------------------
    __syncthreads();
    {
        int e = tid & 127;
        int kk = tid >> 7;  // 0..1
        float2 v = *(const float2*)&ea[(size_t)(ebase + e) * 4 + kk * 2];
        sA[(kk * 2 + 0) * PADA + e] = v.x;
        sA[(kk * 2 + 1) * PADA + e] = v.y;
        if (tid < 128) *(float4*)&sB[tid * 4] = *(const float4*)&w1[(size_t)256 * Dd + tid * 4];
    }
    __syncthreads();
    mma_chunk<4>(sA, sB, acc, e0, c0);

    // ----- epilogue 1: +b1, relu, BN -> sM (k-major: [channel][edge]) ------
    float scale[8], shift[8], bias1[8];
#pragma unroll
    for (int j = 0; j < 8; j++) {
        float s = bng[c0 + j] * rsqrtf(bnv[c0 + j] + EPSBN);
        scale[j] = s;
        shift[j] = bnb[c0 + j] - bnm[c0 + j] * s;
        bias1[j] = b1[c0 + j];
    }
    __syncthreads();
#pragma unroll
    for (int i = 0; i < 8; i++)
#pragma unroll
        for (int j = 0; j < 4; j++) {
            float2 p = unpk(acc[i][j]);
            float t0 = fmaxf(p.x + bias1[2 * j], 0.f);
            float t1 = fmaxf(p.y + bias1[2 * j + 1], 0.f);
            sM[(c0 + 2 * j + 0) * PADA + e0 + i] = fmaf(t0, scale[2 * j], shift[2 * j]);
            sM[(c0 + 2 * j + 1) * PADA + e0 + i] = fmaf(t1, scale[2 * j + 1], shift[2 * j + 1]);
        }

    // ----- GEMM2: K=128, A already resident in sM --------------------------
    u64t acc2[8][4];
#pragma unroll
    for (int i = 0; i < 8; i++)
#pragma unroll
        for (int j = 0; j < 4; j++) acc2[i][j] = 0ull;

    for (int kc = 0; kc < 4; kc++) {
        __syncthreads();
        const float* wsrc = w2 + (size_t)(kc * 32) * Dd;
#pragma unroll
        for (int i = 0; i < 4; i++) {
            int li = tid + i * 256;
            *(float4*)&sB[li * 4] = *(const float4*)&wsrc[li * 4];
        }
        __syncthreads();
        mma_chunk<32>(sM + (size_t)(kc * 32) * PADA, sB, acc2, e0, c0);
    }

    // ----- epilogue 2: +b2, relu, scatter-add ------------------------------
    float bias2[8];
#pragma unroll
    for (int j = 0; j < 8; j++) bias2[j] = b2[c0 + j];
#pragma unroll
    for (int i = 0; i < 8; i++) {
        int d = sDst[e0 + i];
        float* arow = &aggr[(size_t)d * Dd];
#pragma unroll
        for (int j = 0; j < 4; j++) {
            float2 p = unpk(acc2[i][j]);
            atomicAdd(&arow[c0 + 2 * j + 0], fmaxf(p.x + bias2[2 * j], 0.f));
            atomicAdd(&arow[c0 + 2 * j + 1], fmaxf(p.y + bias2[2 * j + 1], 0.f));
        }
    }
}

// ---------------------------------------------------------------------------
// Node kernel: 128-node tile. GEMM1 (K=256: h|aggr) -> relu/BN -> GEMM2
// (K=128) -> relu -> residual add.
// ---------------------------------------------------------------------------
__global__ __launch_bounds__(256, 2) void node_kernel(
    float* __restrict__ h, const float* __restrict__ aggr,
    const float* __restrict__ w1, const float* __restrict__ b1,
    const float* __restrict__ bng, const float* __restrict__ bnb,
    const float* __restrict__ bnm, const float* __restrict__ bnv,
    const float* __restrict__ w2, const float* __restrict__ b2) {
    extern __shared__ float smem[];
    float* sM = smem;
    float* sA = smem;
    float* sB = smem + 128 * PADA;

    const int tid = threadIdx.x;
    const int cx = tid & 15, ey = tid >> 4;
    const int c0 = cx * 8, e0 = ey * 8;
    const int nbase = blockIdx.x * 128;

    const int kq = tid & 7;
    const int er = tid >> 3;

    u64t acc[8][4];
#pragma unroll
    for (int i = 0; i < 8; i++)
#pragma unroll
        for (int j = 0; j < 4; j++) acc[i][j] = 0ull;

    for (int kc = 0; kc < 8; kc++) {
        __syncthreads();
        {
            const int koff = (kc & 3) * 32 + kq * 4;
            const float* base = (kc < 4) ? h : aggr;
#pragma unroll
            for (int p = 0; p < 4; p++) {
                int e = er + p * 32;
                int n = nbase + e;
                if (n > Nn - 1) n = Nn - 1;
                float4 v = *(const float4*)&base[(size_t)n * Dd + koff];
                sA[(kq * 4 + 0) * PADA + e] = v.x;
                sA[(kq * 4 + 1) * PADA + e] = v.y;
                sA[(kq * 4 + 2) * PADA + e] = v.z;
                sA[(kq * 4 + 3) * PADA + e] = v.w;
            }
        }
        {
            const float* wsrc = w1 + (size_t)(kc * 32) * Dd;
#pragma unroll
            for (int i = 0; i < 4; i++) {
                int li = tid + i * 256;
                *(float4*)&sB[li * 4] = *(const float4*)&wsrc[li * 4];
            }
        }
        __syncthreads();
        mma_chunk<32>(sA, sB, acc, e0, c0);
    }

    float scale[8], shift[8], bias1[8];
#pragma unroll
    for (int j = 0; j < 8; j++) {
        float s = bng[c0 + j] * rsqrtf(bnv[c0 + j] + EPSBN);
        scale[j] = s;
        shift[j] = bnb[c0 + j] - bnm[c0 + j] * s;
        bias1[j] = b1[c0 + j];
    }
    __syncthreads();
#pragma unroll
    for (int i = 0; i < 8; i++)
#pragma unroll
        for (int j = 0; j < 4; j++) {
            float2 p = unpk(acc[i][j]);
            float t0 = fmaxf(p.x + bias1[2 * j], 0.f);
            float t1 = fmaxf(p.y + bias1[2 * j + 1], 0.f);
            sM[(c0 + 2 * j + 0) * PADA + e0 + i] = fmaf(t0, scale[2 * j], shift[2 * j]);
            sM[(c0 + 2 * j + 1) * PADA + e0 + i] = fmaf(t1, scale[2 * j + 1], shift[2 * j + 1]);
        }

    u64t acc2[8][4];
#pragma unroll
    for (int i = 0; i < 8; i++)
#pragma unroll
        for (int j = 0; j < 4; j++) acc2[i][j] = 0ull;

    for (int kc = 0; kc < 4; kc++) {
        __syncthreads();
        const float* wsrc = w2 + (size_t)(kc * 32) * Dd;
#pragma unroll
        for (int i = 0; i < 4; i++) {
            int li = tid + i * 256;
            *(float4*)&sB[li * 4] = *(const float4*)&wsrc[li * 4];
        }
        __syncthreads();
        mma_chunk<32>(sM + (size_t)(kc * 32) * PADA, sB, acc2, e0, c0);
    }

    float bias2[8];
#pragma unroll
    for (int j = 0; j < 8; j++) bias2[j] = b2[c0 + j];
#pragma unroll
    for (int i = 0; i < 8; i++) {
        int n = nbase + e0 + i;
        if (n < Nn) {
            float* hr = &h[(size_t)n * Dd];
#pragma unroll
            for (int j = 0; j < 4; j++) {
                float2 p = unpk(acc2[i][j]);
                hr[c0 + 2 * j + 0] += fmaxf(p.x + bias2[2 * j], 0.f);
                hr[c0 + 2 * j + 1] += fmaxf(p.y + bias2[2 * j + 1], 0.f);
            }
        }
    }
}

// ---------------------------------------------------------------------------
__global__ void pool_sum_kernel(const float* __restrict__ h, const int* __restrict__ batch,
                                float* __restrict__ sums, float* __restrict__ cnt) {
    const int c = threadIdx.x;
    const int n0 = blockIdx.x * 64;
    __shared__ int sb[64];
    if (c < 64) {
        int n = n0 + c;
        sb[c] = (n < Nn) ? batch[n] : -1;
    }
    __syncthreads();
    float acc = 0.f;
    int cur = sb[0];
    int cl = 0;
    for (int i = 0; i < 64; i++) {
        int g = sb[i];
        if (g < 0) break;
        if (g != cur) {
            atomicAdd(&sums[cur * Dd + c], acc);
            if (c == 0) atomicAdd(&cnt[cur], (float)cl);
            acc = 0.f;
            cl = 0;
            cur = g;
        }
        acc += h[(size_t)(n0 + i) * Dd + c];
        cl++;
    }
    if (cur >= 0 && cl > 0) {
        atomicAdd(&sums[cur * Dd + c], acc);
        if (c == 0) atomicAdd(&cnt[cur], (float)cl);
    }
}

__global__ void pool_out_kernel(const float* __restrict__ sums, const float* __restrict__ cnt,
                                const float* __restrict__ pw, const float* __restrict__ pb,
                                float* __restrict__ out) {
    const int g = blockIdx.x;
    const int c = threadIdx.x;
    float inv = 1.0f / fmaxf(cnt[g], 1.0f);
    float v = sums[g * Dd + c] * inv * pw[c];
    __shared__ float red[128];
    red[c] = v;
    __syncthreads();
#pragma unroll
    for (int s = 64; s > 0; s >>= 1) {
        if (c < s) red[c] += red[c + s];
        __syncthreads();
    }
    if (c == 0) out[g] = red[0] + pb[0];
}

// ---------------------------------------------------------------------------
extern "C" void kernel_launch(void* const* d_in, const int* in_sizes, int n_in,
                              void* d_out, int out_size) {
    const float* x = (const float*)d_in[0];
    const float* pos = (const float*)d_in[1];
    const int* eidx = (const int*)d_in[2];
    const float* ea = (const float*)d_in[3];
    const int* batch = (const int*)d_in[4];
    const float* lin_w = (const float*)d_in[5];
    const float* lin_b = (const float*)d_in[6];
    const float* mw1 = (const float*)d_in[7];
    const float* mb1 = (const float*)d_in[8];
    const float* mg = (const float*)d_in[9];
    const float* mbb = (const float*)d_in[10];
    const float* mm = (const float*)d_in[11];
    const float* mv = (const float*)d_in[12];
    const float* mw2 = (const float*)d_in[13];
    const float* mb2 = (const float*)d_in[14];
    const float* uw1 = (const float*)d_in[15];
    const float* ub1 = (const float*)d_in[16];
    const float* ug = (const float*)d_in[17];
    const float* ubb = (const float*)d_in[18];
    const float* um = (const float*)d_in[19];
    const float* uv = (const float*)d_in[20];
    const float* uw2 = (const float*)d_in[21];
    const float* ub2 = (const float*)d_in[22];
    const float* pw = (const float*)d_in[23];
    const float* pb = (const float*)d_in[24];
    float* out = (float*)d_out;

    float *h, *aggr, *sums, *cnt;
    cudaGetSymbolAddress((void**)&h, g_h);
    cudaGetSymbolAddress((void**)&aggr, g_aggr);
    cudaGetSymbolAddress((void**)&sums, g_sums);
    cudaGetSymbolAddress((void**)&cnt, g_cnt);

    const int SMEM = (128 * PADA + 32 * Dd) * (int)sizeof(float);  // 83968 B
    cudaFuncSetAttribute(edge_kernel, cudaFuncAttributeMaxDynamicSharedMemorySize, SMEM);
    cudaFuncSetAttribute(node_kernel, cudaFuncAttributeMaxDynamicSharedMemorySize, SMEM);

    lin_in_kernel<<<Nn, 128>>>(x, pos, lin_w, lin_b, h);

    for (int l = 0; l < 4; l++) {
        cudaMemsetAsync(aggr, 0, (size_t)Nn * Dd * sizeof(float), 0);
        edge_kernel<<<Ee / 128, 256, SMEM>>>(
            h, eidx /*src*/, eidx + Ee /*dst*/, ea,
            mw1 + (size_t)l * 260 * Dd, mb1 + l * Dd,
            mg + l * Dd, mbb + l * Dd, mm + l * Dd, mv + l * Dd,
            mw2 + (size_t)l * Dd * Dd, mb2 + l * Dd, aggr);
        node_kernel<<<(Nn + 127) / 128, 256, SMEM>>>(
            h, aggr,
            uw1 + (size_t)l * 256 * Dd, ub1 + l * Dd,
            ug + l * Dd, ubb + l * Dd, um + l * Dd, uv + l * Dd,
            uw2 + (size_t)l * Dd * Dd, ub2 + l * Dd);
    }

    cudaMemsetAsync(sums, 0, Gg * Dd * sizeof(float), 0);
    cudaMemsetAsync(cnt, 0, Gg * sizeof(float), 0);
    pool_sum_kernel<<<(Nn + 63) / 64, 128>>>(h, batch, sums, cnt);
    pool_out_kernel<<<Gg, 128>>>(sums, cnt, pw, pb, out);
}

// round 13
// speedup vs baseline: 1.0568x; 1.0568x over previous
#include <cuda_runtime.h>

#define Nn 100000
#define Ee 1600000
#define Dd 128
#define Gg 64
#define EPSBN 1e-5f
#define PADA 132

typedef unsigned long long u64t;

__device__ float g_h[Nn * Dd];
__device__ float g_aggr[Nn * Dd];
__device__ float g_sums[Gg * Dd];
__device__ float g_cnt[Gg];

// ---- packed fp32 helpers (Blackwell f32x2) --------------------------------
__device__ __forceinline__ void ffma2(u64t& d, u64t a, u64t b) {
    asm("fma.rn.f32x2 %0, %1, %2, %0;" : "+l"(d) : "l"(a), "l"(b));
}
__device__ __forceinline__ u64t rep2(float x) {
    u64t r; asm("mov.b64 %0, {%1, %1};" : "=l"(r) : "f"(x)); return r;
}
__device__ __forceinline__ float2 unpk(u64t v) {
    float2 f; asm("mov.b64 {%0, %1}, %2;" : "=f"(f.x), "=f"(f.y) : "l"(v)); return f;
}

// ---- shared-tile MMA: 8 edges x 8 channels per thread ---------------------
template <int KMAX>
__device__ __forceinline__ void mma_chunk(const float* __restrict__ sA,
                                          const float* __restrict__ sB,
                                          u64t acc[8][4], int e0, int c0) {
#pragma unroll 8
    for (int k = 0; k < KMAX; k++) {
        float4 a01 = *(const float4*)(sA + k * PADA + e0);
        float4 a23 = *(const float4*)(sA + k * PADA + e0 + 4);
        const u64t* br = (const u64t*)(sB + k * Dd + c0);
        u64t b0 = br[0], b1 = br[1], b2 = br[2], b3 = br[3];
        u64t av;
        av = rep2(a01.x); ffma2(acc[0][0], av, b0); ffma2(acc[0][1], av, b1); ffma2(acc[0][2], av, b2); ffma2(acc[0][3], av, b3);
        av = rep2(a01.y); ffma2(acc[1][0], av, b0); ffma2(acc[1][1], av, b1); ffma2(acc[1][2], av, b2); ffma2(acc[1][3], av, b3);
        av = rep2(a01.z); ffma2(acc[2][0], av, b0); ffma2(acc[2][1], av, b1); ffma2(acc[2][2], av, b2); ffma2(acc[2][3], av, b3);
        av = rep2(a01.w); ffma2(acc[3][0], av, b0); ffma2(acc[3][1], av, b1); ffma2(acc[3][2], av, b2); ffma2(acc[3][3], av, b3);
        av = rep2(a23.x); ffma2(acc[4][0], av, b0); ffma2(acc[4][1], av, b1); ffma2(acc[4][2], av, b2); ffma2(acc[4][3], av, b3);
        av = rep2(a23.y); ffma2(acc[5][0], av, b0); ffma2(acc[5][1], av, b1); ffma2(acc[5][2], av, b2); ffma2(acc[5][3], av, b3);
        av = rep2(a23.z); ffma2(acc[6][0], av, b0); ffma2(acc[6][1], av, b1); ffma2(acc[6][2], av, b2); ffma2(acc[6][3], av, b3);
        av = rep2(a23.w); ffma2(acc[7][0], av, b0); ffma2(acc[7][1], av, b1); ffma2(acc[7][2], av, b2); ffma2(acc[7][3], av, b3);
    }
}

// ---------------------------------------------------------------------------
__global__ void lin_in_kernel(const float* __restrict__ x, const float* __restrict__ pos,
                              const float* __restrict__ w, const float* __restrict__ b,
                              float* __restrict__ h) {
    int n = blockIdx.x;
    int c = threadIdx.x;
    __shared__ float f[14];
    if (c < 11) f[c] = x[n * 11 + c];
    else if (c < 14) f[c] = pos[n * 3 + (c - 11)];
    __syncthreads();
    float acc = b[c];
#pragma unroll
    for (int k = 0; k < 14; k++) acc = fmaf(f[k], w[k * Dd + c], acc);
    h[n * Dd + c] = acc;
}

// ---------------------------------------------------------------------------
// Edge kernel: 128-edge tile. GEMM1 (K=260) -> relu/BN -> GEMM2 (K=128)
// -> relu -> atomic scatter-add. sA layout is k-major [k][edge] (PADA=132).
// ---------------------------------------------------------------------------
__global__ __launch_bounds__(256, 2) void edge_kernel(
    const float* __restrict__ h, const int* __restrict__ src, const int* __restrict__ dst,
    const float* __restrict__ ea,
    const float* __restrict__ w1, const float* __restrict__ b1,
    const float* __restrict__ bng, const float* __restrict__ bnb,
    const float* __restrict__ bnm, const float* __restrict__ bnv,
    const float* __restrict__ w2, const float* __restrict__ b2,
    float* __restrict__ aggr) {
    extern __shared__ float smem[];
    float* sM = smem;                 // [128][PADA]
    float* sA = smem;                 // overlay: [32][PADA]
    float* sB = smem + 128 * PADA;    // [32][128]
    __shared__ int sDst[128], sSrc[128];

    const int tid = threadIdx.x;
    const int cx = tid & 15, ey = tid >> 4;
    const int c0 = cx * 8, e0 = ey * 8;
    const int ebase = blockIdx.x * 128;

    if (tid < 128) {
        sDst[tid] = dst[ebase + tid];
        sSrc[tid] = src[ebase + tid];
    }

    const int kq = tid & 7;    // k-quad for staging
    const int er = tid >> 3;   // 0..31

    u64t acc[8][4];
#pragma unroll
    for (int i = 0; i < 8; i++)
#pragma unroll
        for (int j = 0; j < 4; j++) acc[i][j] = 0ull;

    // ----- GEMM1: chunks 0..7 = h[dst]|h[src] ------------------------------
    for (int kc = 0; kc < 8; kc++) {
        __syncthreads();
        {
            const int koff = (kc & 3) * 32 + kq * 4;
            const int* nodes = (kc < 4) ? sDst : sSrc;
#pragma unroll
            for (int p = 0; p < 4; p++) {
                int e = er + p * 32;
                int node = nodes[e];
                float4 v = *(const float4*)&h[(size_t)node * Dd + koff];
                sA[(kq * 4 + 0) * PADA + e] = v.x;
                sA[(kq * 4 + 1) * PADA + e] = v.y;
                sA[(kq * 4 + 2) * PADA + e] = v.z;
                sA[(kq * 4 + 3) * PADA + e] = v.w;
            }
        }
        {
            const float* wsrc = w1 + (size_t)(kc * 32) * Dd;
#pragma unroll
            for (int i = 0; i < 4; i++) {
                int li = tid + i * 256;
                *(float4*)&sB[li * 4] = *(const float4*)&wsrc[li * 4];
            }
        }
        __syncthreads();
        mma_chunk<32>(sA, sB, acc, e0, c0);
    }

    // ----- GEMM1: ragged chunk (edge_attr, 4 k) ----------------------------
    __syncthreads();
    {
        int e = tid & 127;
        int kk = tid >> 7;  // 0..1
        float2 v = *(const float2*)&ea[(size_t)(ebase + e) * 4 + kk * 2];
        sA[(kk * 2 + 0) * PADA + e] = v.x;
        sA[(kk * 2 + 1) * PADA + e] = v.y;
        if (tid < 128) *(float4*)&sB[tid * 4] = *(const float4*)&w1[(size_t)256 * Dd + tid * 4];
    }
    __syncthreads();
    mma_chunk<4>(sA, sB, acc, e0, c0);

    // ----- epilogue 1: +b1, relu, BN -> sM (k-major: [channel][edge]) ------
    float scale[8], shift[8], bias1[8];
#pragma unroll
    for (int j = 0; j < 8; j++) {
        float s = bng[c0 + j] * rsqrtf(bnv[c0 + j] + EPSBN);
        scale[j] = s;
        shift[j] = bnb[c0 + j] - bnm[c0 + j] * s;
        bias1[j] = b1[c0 + j];
    }
    __syncthreads();
#pragma unroll
    for (int i = 0; i < 8; i++)
#pragma unroll
        for (int j = 0; j < 4; j++) {
            float2 p = unpk(acc[i][j]);
            float t0 = fmaxf(p.x + bias1[2 * j], 0.f);
            float t1 = fmaxf(p.y + bias1[2 * j + 1], 0.f);
            sM[(c0 + 2 * j + 0) * PADA + e0 + i] = fmaf(t0, scale[2 * j], shift[2 * j]);
            sM[(c0 + 2 * j + 1) * PADA + e0 + i] = fmaf(t1, scale[2 * j + 1], shift[2 * j + 1]);
        }

    // ----- GEMM2: K=128, A already resident in sM --------------------------
    u64t acc2[8][4];
#pragma unroll
    for (int i = 0; i < 8; i++)
#pragma unroll
        for (int j = 0; j < 4; j++) acc2[i][j] = 0ull;

    for (int kc = 0; kc < 4; kc++) {
        __syncthreads();
        const float* wsrc = w2 + (size_t)(kc * 32) * Dd;
#pragma unroll
        for (int i = 0; i < 4; i++) {
            int li = tid + i * 256;
            *(float4*)&sB[li * 4] = *(const float4*)&wsrc[li * 4];
        }
        __syncthreads();
        mma_chunk<32>(sM + (size_t)(kc * 32) * PADA, sB, acc2, e0, c0);
    }

    // ----- epilogue 2: +b2, relu, scatter-add ------------------------------
    float bias2[8];
#pragma unroll
    for (int j = 0; j < 8; j++) bias2[j] = b2[c0 + j];
#pragma unroll
    for (int i = 0; i < 8; i++) {
        int d = sDst[e0 + i];
        float* arow = &aggr[(size_t)d * Dd];
#pragma unroll
        for (int j = 0; j < 4; j++) {
            float2 p = unpk(acc2[i][j]);
            atomicAdd(&arow[c0 + 2 * j + 0], fmaxf(p.x + bias2[2 * j], 0.f));
            atomicAdd(&arow[c0 + 2 * j + 1], fmaxf(p.y + bias2[2 * j + 1], 0.f));
        }
    }
}

// ---------------------------------------------------------------------------
// Node kernel: 128-node tile. GEMM1 (K=256: h|aggr) -> relu/BN -> GEMM2
// (K=128) -> relu -> residual add.
// ---------------------------------------------------------------------------
__global__ __launch_bounds__(256, 2) void node_kernel(
    float* __restrict__ h, const float* __restrict__ aggr,
    const float* __restrict__ w1, const float* __restrict__ b1,
    const float* __restrict__ bng, const float* __restrict__ bnb,
    const float* __restrict__ bnm, const float* __restrict__ bnv,
    const float* __restrict__ w2, const float* __restrict__ b2) {
    extern __shared__ float smem[];
    float* sM = smem;
    float* sA = smem;
    float* sB = smem + 128 * PADA;

    const int tid = threadIdx.x;
    const int cx = tid & 15, ey = tid >> 4;
    const int c0 = cx * 8, e0 = ey * 8;
    const int nbase = blockIdx.x * 128;

    const int kq = tid & 7;
    const int er = tid >> 3;

    u64t acc[8][4];
#pragma unroll
    for (int i = 0; i < 8; i++)
#pragma unroll
        for (int j = 0; j < 4; j++) acc[i][j] = 0ull;

    for (int kc = 0; kc < 8; kc++) {
        __syncthreads();
        {
            const int koff = (kc & 3) * 32 + kq * 4;
            const float* base = (kc < 4) ? h : aggr;
#pragma unroll
            for (int p = 0; p < 4; p++) {
                int e = er + p * 32;
                int n = nbase + e;
                if (n > Nn - 1) n = Nn - 1;
                float4 v = *(const float4*)&base[(size_t)n * Dd + koff];
                sA[(kq * 4 + 0) * PADA + e] = v.x;
                sA[(kq * 4 + 1) * PADA + e] = v.y;
                sA[(kq * 4 + 2) * PADA + e] = v.z;
                sA[(kq * 4 + 3) * PADA + e] = v.w;
            }
        }
        {
            const float* wsrc = w1 + (size_t)(kc * 32) * Dd;
#pragma unroll
            for (int i = 0; i < 4; i++) {
                int li = tid + i * 256;
                *(float4*)&sB[li * 4] = *(const float4*)&wsrc[li * 4];
            }
        }
        __syncthreads();
        mma_chunk<32>(sA, sB, acc, e0, c0);
    }

    float scale[8], shift[8], bias1[8];
#pragma unroll
    for (int j = 0; j < 8; j++) {
        float s = bng[c0 + j] * rsqrtf(bnv[c0 + j] + EPSBN);
        scale[j] = s;
        shift[j] = bnb[c0 + j] - bnm[c0 + j] * s;
        bias1[j] = b1[c0 + j];
    }
    __syncthreads();
#pragma unroll
    for (int i = 0; i < 8; i++)
#pragma unroll
        for (int j = 0; j < 4; j++) {
            float2 p = unpk(acc[i][j]);
            float t0 = fmaxf(p.x + bias1[2 * j], 0.f);
            float t1 = fmaxf(p.y + bias1[2 * j + 1], 0.f);
            sM[(c0 + 2 * j + 0) * PADA + e0 + i] = fmaf(t0, scale[2 * j], shift[2 * j]);
            sM[(c0 + 2 * j + 1) * PADA + e0 + i] = fmaf(t1, scale[2 * j + 1], shift[2 * j + 1]);
        }

    u64t acc2[8][4];
#pragma unroll
    for (int i = 0; i < 8; i++)
#pragma unroll
        for (int j = 0; j < 4; j++) acc2[i][j] = 0ull;

    for (int kc = 0; kc < 4; kc++) {
        __syncthreads();
        const float* wsrc = w2 + (size_t)(kc * 32) * Dd;
#pragma unroll
        for (int i = 0; i < 4; i++) {
            int li = tid + i * 256;
            *(float4*)&sB[li * 4] = *(const float4*)&wsrc[li * 4];
        }
        __syncthreads();
        mma_chunk<32>(sM + (size_t)(kc * 32) * PADA, sB, acc2, e0, c0);
    }

    float bias2[8];
#pragma unroll
    for (int j = 0; j < 8; j++) bias2[j] = b2[c0 + j];
#pragma unroll
    for (int i = 0; i < 8; i++) {
        int n = nbase + e0 + i;
        if (n < Nn) {
            float* hr = &h[(size_t)n * Dd];
#pragma unroll
            for (int j = 0; j < 4; j++) {
                float2 p = unpk(acc2[i][j]);
                hr[c0 + 2 * j + 0] += fmaxf(p.x + bias2[2 * j], 0.f);
                hr[c0 + 2 * j + 1] += fmaxf(p.y + bias2[2 * j + 1], 0.f);
            }
        }
    }
}

// ---------------------------------------------------------------------------
__global__ void pool_sum_kernel(const float* __restrict__ h, const int* __restrict__ batch,
                                float* __restrict__ sums, float* __restrict__ cnt) {
    const int c = threadIdx.x;
    const int n0 = blockIdx.x * 64;
    __shared__ int sb[64];
    if (c < 64) {
        int n = n0 + c;
        sb[c] = (n < Nn) ? batch[n] : -1;
    }
    __syncthreads();
    float acc = 0.f;
    int cur = sb[0];
    int cl = 0;
    for (int i = 0; i < 64; i++) {
        int g = sb[i];
        if (g < 0) break;
        if (g != cur) {
            atomicAdd(&sums[cur * Dd + c], acc);
            if (c == 0) atomicAdd(&cnt[cur], (float)cl);
            acc = 0.f;
            cl = 0;
            cur = g;
        }
        acc += h[(size_t)(n0 + i) * Dd + c];
        cl++;
    }
    if (cur >= 0 && cl > 0) {
        atomicAdd(&sums[cur * Dd + c], acc);
        if (c == 0) atomicAdd(&cnt[cur], (float)cl);
    }
}

__global__ void pool_out_kernel(const float* __restrict__ sums, const float* __restrict__ cnt,
                                const float* __restrict__ pw, const float* __restrict__ pb,
                                float* __restrict__ out) {
    const int g = blockIdx.x;
    const int c = threadIdx.x;
    float inv = 1.0f / fmaxf(cnt[g], 1.0f);
    float v = sums[g * Dd + c] * inv * pw[c];
    __shared__ float red[128];
    red[c] = v;
    __syncthreads();
#pragma unroll
    for (int s = 64; s > 0; s >>= 1) {
        if (c < s) red[c] += red[c + s];
        __syncthreads();
    }
    if (c == 0) out[g] = red[0] + pb[0];
}

// ---------------------------------------------------------------------------
extern "C" void kernel_launch(void* const* d_in, const int* in_sizes, int n_in,
                              void* d_out, int out_size) {
    const float* x = (const float*)d_in[0];
    const float* pos = (const float*)d_in[1];
    const int* eidx = (const int*)d_in[2];
    const float* ea = (const float*)d_in[3];
    const int* batch = (const int*)d_in[4];
    const float* lin_w = (const float*)d_in[5];
    const float* lin_b = (const float*)d_in[6];
    const float* mw1 = (const float*)d_in[7];
    const float* mb1 = (const float*)d_in[8];
    const float* mg = (const float*)d_in[9];
    const float* mbb = (const float*)d_in[10];
    const float* mm = (const float*)d_in[11];
    const float* mv = (const float*)d_in[12];
    const float* mw2 = (const float*)d_in[13];
    const float* mb2 = (const float*)d_in[14];
    const float* uw1 = (const float*)d_in[15];
    const float* ub1 = (const float*)d_in[16];
    const float* ug = (const float*)d_in[17];
    const float* ubb = (const float*)d_in[18];
    const float* um = (const float*)d_in[19];
    const float* uv = (const float*)d_in[20];
    const float* uw2 = (const float*)d_in[21];
    const float* ub2 = (const float*)d_in[22];
    const float* pw = (const float*)d_in[23];
    const float* pb = (const float*)d_in[24];
    float* out = (float*)d_out;

    float *h, *aggr, *sums, *cnt;
    cudaGetSymbolAddress((void**)&h, g_h);
    cudaGetSymbolAddress((void**)&aggr, g_aggr);
    cudaGetSymbolAddress((void**)&sums, g_sums);
    cudaGetSymbolAddress((void**)&cnt, g_cnt);

    const int SMEM = (128 * PADA + 32 * Dd) * (int)sizeof(float);  // 83968 B
    cudaFuncSetAttribute(edge_kernel, cudaFuncAttributeMaxDynamicSharedMemorySize, SMEM);
    cudaFuncSetAttribute(node_kernel, cudaFuncAttributeMaxDynamicSharedMemorySize, SMEM);

    lin_in_kernel<<<Nn, 128>>>(x, pos, lin_w, lin_b, h);

    for (int l = 0; l < 4; l++) {
        cudaMemsetAsync(aggr, 0, (size_t)Nn * Dd * sizeof(float), 0);
        edge_kernel<<<Ee / 128, 256, SMEM>>>(
            h, eidx /*src*/, eidx + Ee /*dst*/, ea,
            mw1 + (size_t)l * 260 * Dd, mb1 + l * Dd,
            mg + l * Dd, mbb + l * Dd, mm + l * Dd, mv + l * Dd,
            mw2 + (size_t)l * Dd * Dd, mb2 + l * Dd, aggr);
        node_kernel<<<(Nn + 127) / 128, 256, SMEM>>>(
            h, aggr,
            uw1 + (size_t)l * 256 * Dd, ub1 + l * Dd,
            ug + l * Dd, ubb + l * Dd, um + l * Dd, uv + l * Dd,
            uw2 + (size_t)l * Dd * Dd, ub2 + l * Dd);
    }

    cudaMemsetAsync(sums, 0, Gg * Dd * sizeof(float), 0);
    cudaMemsetAsync(cnt, 0, Gg * sizeof(float), 0);
    pool_sum_kernel<<<(Nn + 63) / 64, 128>>>(h, batch, sums, cnt);
    pool_out_kernel<<<Gg, 128>>>(sums, cnt, pw, pb, out);
}